// round 15
// baseline (speedup 1.0000x reference)
#include <cuda_runtime.h>
#include <cstdint>

#define NROW 16384      // B
#define MDIM 4096       // M*DV

// 256 MB scratch for memory_pre (fp32, exact output base)
__device__ float g_mpre[(size_t)NROW * MDIM];

__device__ __forceinline__ float sigf(float x) { return 1.0f / (1.0f + __expf(-x)); }

// m16n8k8 tf32 MMA, D accumulates in place. Raw fp32 registers are passed;
// the tensor core reads only the tf32 bits (implicit truncation).
__device__ __forceinline__ void mma8(float* c, float a0, float a1, float a2, float a3,
                                     float b0, float b1) {
    asm volatile(
        "mma.sync.aligned.m16n8k8.row.col.f32.tf32.tf32.f32 "
        "{%0,%1,%2,%3}, {%4,%5,%6,%7}, {%8,%9}, {%0,%1,%2,%3};\n"
        : "+f"(c[0]), "+f"(c[1]), "+f"(c[2]), "+f"(c[3])
        : "r"(__float_as_uint(a0)), "r"(__float_as_uint(a1)),
          "r"(__float_as_uint(a2)), "r"(__float_as_uint(a3)),
          "r"(__float_as_uint(b0)), "r"(__float_as_uint(b1)));
}

// 16-byte async copy global -> shared (LDGSTS)
__device__ __forceinline__ void cpa16(uint32_t dst, const void* src) {
    asm volatile("cp.async.cg.shared.global [%0], [%1], 16;\n" :: "r"(dst), "l"(src));
}
#define CP_COMMIT() asm volatile("cp.async.commit_group;\n" ::: "memory")
#define CP_WAIT0()  asm volatile("cp.async.wait_group 0;\n" ::: "memory")
#define CP_WAIT1()  asm volatile("cp.async.wait_group 1;\n" ::: "memory")

// Shared memory regions (float offsets). A-operand arrays use LD % 32 == 4,
// B-operand (weight) arrays use LD % 32 == 8 or == 4 -> conflict-free frag loads.
// Phase-0: B[0:8704] Wc0 [64][136]; B[8704:13056] mv ping buffer [64][68]
// Phase-1: B[0:9216] Wm1 [128][72]; B[9216:13568] Wemv [64][68];
//          then B[0:4352] Wzmv [64][68]; B[4352:8704] Wamv [64][68]
#define OFF_A 0                    // 64x132 content0; later reused as [64][68] E/erase
#define OFF_B 8448                 // weights; epilogue: +4608 ck; +8960 logits/ww
#define OFF_C (8448 + 13568)       // 22016: [64][68] mv/mp/zt/aA/add (A-operand, LD 68)
#define SMEM_FLOATS (OFF_C + 4352) // 26368 floats = 105472 bytes

__global__ void __launch_bounds__(256, 2)
memnet_tc(const float* __restrict__ ck, const float* __restrict__ qa,
          const float* __restrict__ mk, const float* __restrict__ mv,
          const float* __restrict__ We, const float* __restrict__ be,
          const float* __restrict__ Wemv, const float* __restrict__ bemv,
          const float* __restrict__ Wza, const float* __restrict__ bza,
          const float* __restrict__ Wamv, const float* __restrict__ bamv,
          const float* __restrict__ Wc0, const float* __restrict__ bc0,
          const float* __restrict__ Wm1, const float* __restrict__ bm1,
          const float* __restrict__ Wz, const float* __restrict__ bz,
          const float* __restrict__ Wzmv, const float* __restrict__ bzmv,
          float* __restrict__ out)
{
    extern __shared__ float sm[];
    const uint32_t smb = (uint32_t)__cvta_generic_to_shared(sm);
    const int tid = threadIdx.x;
    const int w = tid >> 5;
    const int lane = tid & 31;
    const int g = lane >> 2;         // 0..7
    const int t = lane & 3;          // 0..3
    const int rb = blockIdx.x * 64;

    // warp tilings
    // phase0: warp grid 2(m) x 2(n) x 2(k-split); each warp m32 x n64, K-half 32
    const int wm0 = (w & 1) * 32, wn0 = ((w >> 1) & 1) * 64, kh0 = (w >> 2) * 32;
    const int wm1 = (w & 3) * 16, wn1 = (w >> 2) * 32;   // T2: m16 x n32 (out 64x64)
    const int wmE = (w & 1) * 32, wnE = (w >> 1) * 48;   // EZA: m32 x n48 (out 64x192)

    // =================== Phase 0: content0 ===================
    float acc0[2][8][4];
#pragma unroll
    for (int mi = 0; mi < 2; mi++)
#pragma unroll
        for (int j = 0; j < 8; j++)
#pragma unroll
            for (int e = 0; e < 4; e++) acc0[mi][j][e] = 0.0f;

    // prologue: prefetch mv(0) into C (buffer 0)
#pragma unroll
    for (int l = 0; l < 4; l++) {
        int idx = tid + l * 256, r = idx >> 4, k4 = idx & 15;
        cpa16(smb + (uint32_t)(OFF_C + r * 68 + k4 * 4) * 4,
              mv + (size_t)(rb + r) * MDIM + k4 * 4);
    }
    CP_COMMIT();

#pragma unroll 1
    for (int c = 0; c < 64; c++) {
        __syncthreads();
        // stage Wc0 chunk -> B[0:8704] [64][136]
#pragma unroll
        for (int l = 0; l < 8; l++) {
            int idx = tid + l * 256, k = idx >> 5, n4 = idx & 31;
            cpa16(smb + (uint32_t)(OFF_B + k * 136 + n4 * 4) * 4,
                  Wc0 + (size_t)(c * 64 + k) * 128 + n4 * 4);
        }
        CP_COMMIT();
        if (c < 63) {
            // prefetch mv(c+1) into the other buffer; keep it in flight
            int mvoff = ((c + 1) & 1) ? (OFF_B + 8704) : OFF_C;
#pragma unroll
            for (int l = 0; l < 4; l++) {
                int idx = tid + l * 256, r = idx >> 4, k4 = idx & 15;
                cpa16(smb + (uint32_t)(mvoff + r * 68 + k4 * 4) * 4,
                      mv + (size_t)(rb + r) * MDIM + (c + 1) * 64 + k4 * 4);
            }
            CP_COMMIT();
            CP_WAIT1();       // mv(c) + Wc0(c) done; mv(c+1) may fly
        } else {
            CP_WAIT0();
        }
        __syncthreads();
        const float* A = (c & 1) ? (sm + OFF_B + 8704) : (sm + OFF_C);
        const float* Bw = sm + OFF_B;
#pragma unroll
        for (int k8 = 0; k8 < 4; k8++) {
            int kk = kh0 + k8 * 8 + t;
            float a[2][4];
#pragma unroll
            for (int mi = 0; mi < 2; mi++) {
                int r = wm0 + mi * 16 + g;
                a[mi][0] = A[r * 68 + kk];
                a[mi][1] = A[(r + 8) * 68 + kk];
                a[mi][2] = A[r * 68 + kk + 4];
                a[mi][3] = A[(r + 8) * 68 + kk + 4];
            }
#pragma unroll
            for (int j = 0; j < 8; j++) {
                float b0 = Bw[kk * 136 + wn0 + j * 8 + g];
                float b1 = Bw[(kk + 4) * 136 + wn0 + j * 8 + g];
                mma8(acc0[0][j], a[0][0], a[0][1], a[0][2], a[0][3], b0, b1);
                mma8(acc0[1][j], a[1][0], a[1][1], a[1][2], a[1][3], b0, b1);
            }
        }
    }
    // K-split reduction: warps 4-7 dump partials into OFF_B, warps 0-3 add.
    __syncthreads();
    if (w >= 4) {
#pragma unroll
        for (int mi = 0; mi < 2; mi++)
#pragma unroll
            for (int j = 0; j < 8; j++)
#pragma unroll
                for (int ee = 0; ee < 4; ee++) {
                    int r = wm0 + mi * 16 + g + ((ee >= 2) ? 8 : 0);
                    int col = wn0 + j * 8 + 2 * t + (ee & 1);
                    sm[OFF_B + r * 136 + col] = acc0[mi][j][ee];
                }
    }
    __syncthreads();
    if (w < 4) {
#pragma unroll
        for (int mi = 0; mi < 2; mi++)
#pragma unroll
            for (int j = 0; j < 8; j++)
#pragma unroll
                for (int ee = 0; ee < 4; ee++) {
                    int r = wm0 + mi * 16 + g + ((ee >= 2) ? 8 : 0);
                    int col = wn0 + j * 8 + 2 * t + (ee & 1);
                    acc0[mi][j][ee] += sm[OFF_B + r * 136 + col];
                }
        // content0 epilogue -> s_c0 [64][132] (raw fp32; MMA truncates on use)
#pragma unroll
        for (int mi = 0; mi < 2; mi++)
#pragma unroll
            for (int j = 0; j < 8; j++)
#pragma unroll
                for (int e = 0; e < 2; e++) {
                    int col = wn0 + j * 8 + 2 * t + e;
                    float bc = bc0[col];
                    int r = wm0 + mi * 16 + g;
                    float q0 = qa[(size_t)(rb + r) * 128 + col];
                    float q1 = qa[(size_t)(rb + r + 8) * 128 + col];
                    sm[OFF_A + r * 132 + col]       = q0 * sigf(acc0[mi][j][e] + bc);
                    sm[OFF_A + (r + 8) * 132 + col] = q1 * sigf(acc0[mi][j][2 + e] + bc);
                }
    }

    // =================== Phase 1: gate + memory_pre + EZA reductions ===================
    float aE[2][6][4];
#pragma unroll
    for (int mi = 0; mi < 2; mi++)
#pragma unroll
        for (int j = 0; j < 6; j++)
#pragma unroll
            for (int e = 0; e < 4; e++) aE[mi][j][e] = 0.0f;

    // EZA B-region base offsets (constant across chunks):
    // E -> B[9216:13568] [64][68], Z -> B[0:4352] [64][68], A -> B[4352:8704] [64][68]
    int ezaO[6];
#pragma unroll
    for (int j = 0; j < 6; j++) {
        int n = wnE + j * 8;
        ezaO[j] = (n < 64) ? (OFF_B + 9216 + n)
                : (n < 128) ? (OFF_B + (n - 64))
                            : (OFF_B + 4352 + (n - 128));
    }

#pragma unroll 1
    for (int c = 0; c < 64; c++) {
        __syncthreads();   // (a): EZA(c-1) done reading B/C
        // top stage: Wm1 [128][72], Wemv [64][68] -> BE, mv [64][68] -> C
#pragma unroll
        for (int h = 0; h < 8; h++) {
            int idx = tid + h * 256, k = idx >> 4, n4 = idx & 15;
            cpa16(smb + (uint32_t)(OFF_B + k * 72 + n4 * 4) * 4,
                  Wm1 + (size_t)k * MDIM + c * 64 + n4 * 4);
        }
#pragma unroll
        for (int l = 0; l < 4; l++) {
            int idx = tid + l * 256, r = idx >> 4, k4 = idx & 15;
            cpa16(smb + (uint32_t)(OFF_B + 9216 + r * 68 + k4 * 4) * 4,
                  Wemv + (size_t)(c * 64 + r) * 64 + k4 * 4);
            cpa16(smb + (uint32_t)(OFF_C + r * 68 + k4 * 4) * 4,
                  mv + (size_t)(rb + r) * MDIM + c * 64 + k4 * 4);
        }
        CP_COMMIT(); CP_WAIT0();
        __syncthreads();   // (b)
        // gate GEMM (T2): A = content0 (K=128), B = Wm1 chunk
        float gg[4][4];
#pragma unroll
        for (int j = 0; j < 4; j++)
#pragma unroll
            for (int e = 0; e < 4; e++) gg[j][e] = 0.0f;
        {
            const float* A = sm + OFF_A;
            const float* Bw = sm + OFF_B;
#pragma unroll
            for (int k8 = 0; k8 < 16; k8++) {
                int kk = k8 * 8 + t;
                int r = wm1 + g;
                float a0 = A[r * 132 + kk], a1 = A[(r + 8) * 132 + kk];
                float a2 = A[r * 132 + kk + 4], a3 = A[(r + 8) * 132 + kk + 4];
#pragma unroll
                for (int j = 0; j < 4; j++) {
                    float b0 = Bw[kk * 72 + wn1 + j * 8 + g];
                    float b1 = Bw[(kk + 4) * 72 + wn1 + j * 8 + g];
                    mma8(gg[j], a0, a1, a2, a3, b0, b1);
                }
            }
        }
        // memory_pre in-place in C (each cell owned by exactly one thread)
#pragma unroll
        for (int j = 0; j < 4; j++) {
            int colb = wn1 + j * 8 + 2 * t;
            float2 bm = *(const float2*)(bm1 + c * 64 + colb);
            int ra = wm1 + g, rc = wm1 + g + 8;
            float2 m0 = *(const float2*)(sm + OFF_C + ra * 68 + colb);
            float2 m1 = *(const float2*)(sm + OFF_C + rc * 68 + colb);
            float2 p0, p1;
            p0.x = m0.x * sigf(gg[j][0] + bm.x);
            p0.y = m0.y * sigf(gg[j][1] + bm.y);
            p1.x = m1.x * sigf(gg[j][2] + bm.x);
            p1.y = m1.y * sigf(gg[j][3] + bm.y);
            *(float2*)(sm + OFF_C + ra * 68 + colb) = p0;
            *(float2*)(sm + OFF_C + rc * 68 + colb) = p1;
        }
        __syncthreads();   // (c): mp visible; gate done reading B[0:9216]
        // second stage: Wzmv -> B[0:4352], Wamv -> B[4352:8704] (hidden under mpre copy)
#pragma unroll
        for (int l = 0; l < 4; l++) {
            int idx = tid + l * 256, r = idx >> 4, k4 = idx & 15;
            size_t go = (size_t)(c * 64 + r) * 64 + k4 * 4;
            cpa16(smb + (uint32_t)(OFF_B + r * 68 + k4 * 4) * 4,        Wzmv + go);
            cpa16(smb + (uint32_t)(OFF_B + 4352 + r * 68 + k4 * 4) * 4, Wamv + go);
        }
        CP_COMMIT();
        // copy mp -> g_mpre (coalesced) while Wz/Wa copies are in flight
        {
            float4 mbuf[4];
#pragma unroll
            for (int l = 0; l < 4; l++) {
                int idx = tid + l * 256, r = idx >> 4, k4 = idx & 15;
                mbuf[l] = *(const float4*)(sm + OFF_C + r * 68 + k4 * 4);
            }
#pragma unroll
            for (int l = 0; l < 4; l++) {
                int idx = tid + l * 256, r = idx >> 4, k4 = idx & 15;
                *(float4*)(g_mpre + (size_t)(rb + r) * MDIM + c * 64 + k4 * 4) = mbuf[l];
            }
        }
        CP_WAIT0();
        __syncthreads();   // (d)
        // EZA GEMM: A = mp (raw fp32), B split across three [64][68] regions, K=64
        {
            const float* A = sm + OFF_C;
#pragma unroll
            for (int k8 = 0; k8 < 8; k8++) {
                int kk = k8 * 8 + t;
                float a[2][4];
#pragma unroll
                for (int mi = 0; mi < 2; mi++) {
                    int r = wmE + mi * 16 + g;
                    a[mi][0] = A[r * 68 + kk];
                    a[mi][1] = A[(r + 8) * 68 + kk];
                    a[mi][2] = A[r * 68 + kk + 4];
                    a[mi][3] = A[(r + 8) * 68 + kk + 4];
                }
#pragma unroll
                for (int j = 0; j < 6; j++) {
                    float b0 = sm[ezaO[j] + kk * 68 + g];
                    float b1 = sm[ezaO[j] + (kk + 4) * 68 + g];
                    mma8(aE[0][j], a[0][0], a[0][1], a[0][2], a[0][3], b0, b1);
                    mma8(aE[1][j], a[1][0], a[1][1], a[1][2], a[1][3], b0, b1);
                }
            }
        }
    }
    __syncthreads();

    // =================== Epilogue ===================
    // qe = content0 @ We (K=128)
#pragma unroll
    for (int l = 0; l < 8; l++) {
        int idx = tid + l * 256, k = idx >> 4, n4 = idx & 15;
        *(float4*)(sm + OFF_B + k * 72 + n4 * 4) =
            *(const float4*)(We + (size_t)k * 64 + n4 * 4);
    }
    __syncthreads();
    float qe[4][4];
#pragma unroll
    for (int j = 0; j < 4; j++)
#pragma unroll
        for (int e = 0; e < 4; e++) qe[j][e] = 0.0f;
    {
        const float* A = sm + OFF_A;
        const float* Bw = sm + OFF_B;
#pragma unroll
        for (int k8 = 0; k8 < 16; k8++) {
            int kk = k8 * 8 + t;
            int r = wm1 + g;
            float a0 = A[r * 132 + kk], a1 = A[(r + 8) * 132 + kk];
            float a2 = A[r * 132 + kk + 4], a3 = A[(r + 8) * 132 + kk + 4];
#pragma unroll
            for (int j = 0; j < 4; j++) {
                float b0 = Bw[kk * 72 + wn1 + j * 8 + g];
                float b1 = Bw[(kk + 4) * 72 + wn1 + j * 8 + g];
                mma8(qe[j], a0, a1, a2, a3, b0, b1);
            }
        }
    }
    __syncthreads();
    // qz = content0 @ Wz
#pragma unroll
    for (int l = 0; l < 8; l++) {
        int idx = tid + l * 256, k = idx >> 4, n4 = idx & 15;
        *(float4*)(sm + OFF_B + k * 72 + n4 * 4) =
            *(const float4*)(Wz + (size_t)k * 64 + n4 * 4);
    }
    __syncthreads();
    float qz[4][4];
#pragma unroll
    for (int j = 0; j < 4; j++)
#pragma unroll
        for (int e = 0; e < 4; e++) qz[j][e] = 0.0f;
    {
        const float* A = sm + OFF_A;
        const float* Bw = sm + OFF_B;
#pragma unroll
        for (int k8 = 0; k8 < 16; k8++) {
            int kk = k8 * 8 + t;
            int r = wm1 + g;
            float a0 = A[r * 132 + kk], a1 = A[(r + 8) * 132 + kk];
            float a2 = A[r * 132 + kk + 4], a3 = A[(r + 8) * 132 + kk + 4];
#pragma unroll
            for (int j = 0; j < 4; j++) {
                float b0 = Bw[kk * 72 + wn1 + j * 8 + g];
                float b1 = Bw[(kk + 4) * 72 + wn1 + j * 8 + g];
                mma8(qz[j], a0, a1, a2, a3, b0, b1);
            }
        }
    }
    __syncthreads();
    // scatter E -> region A [64][68], Z -> region C [64][68]; keep A-part in regs
#pragma unroll
    for (int mi = 0; mi < 2; mi++)
#pragma unroll
        for (int j = 0; j < 6; j++)
#pragma unroll
            for (int ee = 0; ee < 4; ee++) {
                int n = wnE + j * 8 + 2 * t + (ee & 1);
                int r = wmE + mi * 16 + g + ((ee >= 2) ? 8 : 0);
                float v = aE[mi][j][ee];
                if (n < 64)       sm[OFF_A + r * 68 + n] = v;
                else if (n < 128) sm[OFF_C + r * 68 + (n - 64)] = v;
            }
    __syncthreads();
    // erase & zt at T2 positions (in-place rewrite by owner thread)
#pragma unroll
    for (int j = 0; j < 4; j++)
#pragma unroll
        for (int e = 0; e < 2; e++) {
            int col = wn1 + j * 8 + 2 * t + e;
            float bev = be[col], bem = bemv[col];
            float bzv = bz[col], bzm = bzmv[col];
#pragma unroll
            for (int rr = 0; rr < 2; rr++) {
                int r = wm1 + g + rr * 8;
                int ci = rr * 2 + e;
                float E = sm[OFF_A + r * 68 + col];
                float Z = sm[OFF_C + r * 68 + col];
                float er = sigf(sigf(qe[j][ci] + bev) + sigf(E + bem));
                float zt = sigf(qz[j][ci] + bzv + Z + bzm);
                sm[OFF_A + r * 68 + col] = er;
                sm[OFF_C + r * 68 + col] = zt;
            }
        }
    __syncthreads();
    // mk^T -> B[0:4608], ck -> B+4608 [64][68]
#pragma unroll
    for (int l = 0; l < 4; l++) {
        int idx = tid + l * 256, m = idx >> 4, k4 = idx & 15;
        float4 v = *(const float4*)(mk + (size_t)m * 64 + k4 * 4);
        sm[OFF_B + (k4 * 4 + 0) * 72 + m] = v.x;
        sm[OFF_B + (k4 * 4 + 1) * 72 + m] = v.y;
        sm[OFF_B + (k4 * 4 + 2) * 72 + m] = v.z;
        sm[OFF_B + (k4 * 4 + 3) * 72 + m] = v.w;
        *(float4*)(sm + OFF_B + 4608 + m * 68 + k4 * 4) =
            *(const float4*)(ck + (size_t)(rb + m) * 64 + k4 * 4);
    }
    __syncthreads();
    // logits = ck @ mk^T (K=64) -> B+8960 [64][68]
    {
        float lg[4][4];
#pragma unroll
        for (int j = 0; j < 4; j++)
#pragma unroll
            for (int e = 0; e < 4; e++) lg[j][e] = 0.0f;
        const float* A = sm + OFF_B + 4608;
        const float* Bw = sm + OFF_B;
#pragma unroll
        for (int k8 = 0; k8 < 8; k8++) {
            int kk = k8 * 8 + t;
            int r = wm1 + g;
            float a0 = A[r * 68 + kk], a1 = A[(r + 8) * 68 + kk];
            float a2 = A[r * 68 + kk + 4], a3 = A[(r + 8) * 68 + kk + 4];
#pragma unroll
            for (int j = 0; j < 4; j++) {
                float b0 = Bw[kk * 72 + wn1 + j * 8 + g];
                float b1 = Bw[(kk + 4) * 72 + wn1 + j * 8 + g];
                mma8(lg[j], a0, a1, a2, a3, b0, b1);
            }
        }
#pragma unroll
        for (int j = 0; j < 4; j++)
#pragma unroll
            for (int ee = 0; ee < 4; ee++) {
                int col = wn1 + j * 8 + 2 * t + (ee & 1);
                int r = wm1 + g + ((ee >= 2) ? 8 : 0);
                sm[OFF_B + 8960 + r * 68 + col] = lg[j][ee];
            }
    }
    __syncthreads();
    // row softmax over 64 slots -> write weights (in place)
    if (tid < 64) {
        float* row = sm + OFF_B + 8960 + tid * 68;
        float mx = row[0];
        for (int s = 1; s < 64; s++) mx = fmaxf(mx, row[s]);
        float sum = 0.0f;
        for (int s = 0; s < 64; s++) { float e = __expf(row[s] - mx); row[s] = e; sum += e; }
        float inv = 1.0f / sum;
        for (int s = 0; s < 64; s++) row[s] *= inv;
    }
    __syncthreads();
    // Wza -> B[0:4608]
#pragma unroll
    for (int l = 0; l < 4; l++) {
        int idx = tid + l * 256, k = idx >> 4, d4 = idx & 15;
        *(float4*)(sm + OFF_B + k * 72 + d4 * 4) =
            *(const float4*)(Wza + (size_t)k * 64 + d4 * 4);
    }
    __syncthreads();
    // za = zt @ Wza (K=64)
    float za[4][4];
#pragma unroll
    for (int j = 0; j < 4; j++)
#pragma unroll
        for (int e = 0; e < 4; e++) za[j][e] = 0.0f;
    {
        const float* A = sm + OFF_C;
        const float* Bw = sm + OFF_B;
#pragma unroll
        for (int k8 = 0; k8 < 8; k8++) {
            int kk = k8 * 8 + t;
            int r = wm1 + g;
            float a0 = A[r * 68 + kk], a1 = A[(r + 8) * 68 + kk];
            float a2 = A[r * 68 + kk + 4], a3 = A[(r + 8) * 68 + kk + 4];
#pragma unroll
            for (int j = 0; j < 4; j++) {
                float b0 = Bw[kk * 72 + wn1 + j * 8 + g];
                float b1 = Bw[(kk + 4) * 72 + wn1 + j * 8 + g];
                mma8(za[j], a0, a1, a2, a3, b0, b1);
            }
        }
    }
    __syncthreads();
    // scatter A-part of EZA -> region C (overwrites consumed zt)
#pragma unroll
    for (int mi = 0; mi < 2; mi++)
#pragma unroll
        for (int j = 0; j < 6; j++)
#pragma unroll
            for (int ee = 0; ee < 4; ee++) {
                int n = wnE + j * 8 + 2 * t + (ee & 1);
                if (n >= 128) {
                    int r = wmE + mi * 16 + g + ((ee >= 2) ? 8 : 0);
                    sm[OFF_C + r * 68 + (n - 128)] = aE[mi][j][ee];
                }
            }
    __syncthreads();
    // add signal at T2 positions (in-place)
#pragma unroll
    for (int j = 0; j < 4; j++)
#pragma unroll
        for (int e = 0; e < 2; e++) {
            int col = wn1 + j * 8 + 2 * t + e;
            float bzav = bza[col], bam = bamv[col];
#pragma unroll
            for (int rr = 0; rr < 2; rr++) {
                int r = wm1 + g + rr * 8;
                int ci = rr * 2 + e;
                float Aa = sm[OFF_C + r * 68 + col];
                float ad = tanhf(tanhf(za[j][ci] + bzav) + tanhf(Aa + bam));
                sm[OFF_C + r * 68 + col] = ad;
            }
        }
    __syncthreads();

    // =================== Final pass ===================
    {
        const int tx = tid & 15, ty = tid >> 4;
#pragma unroll 1
        for (int c = 0; c < 64; c++) {
#pragma unroll
            for (int i = 0; i < 4; i++) {
                int r = ty * 4 + i;
                int row = rb + r;
                float wv = sm[OFF_B + 8960 + r * 68 + c];
                float4 mp = *(const float4*)(g_mpre + (size_t)row * MDIM + c * 64 + tx * 4);
                float4 e4 = *(const float4*)(sm + OFF_A + r * 68 + tx * 4);
                float4 a4 = *(const float4*)(sm + OFF_C + r * 68 + tx * 4);
                float4 o;
                o.x = mp.x * (1.0f - wv * e4.x) + wv * a4.x;
                o.y = mp.y * (1.0f - wv * e4.y) + wv * a4.y;
                o.z = mp.z * (1.0f - wv * e4.z) + wv * a4.z;
                o.w = mp.w * (1.0f - wv * e4.w) + wv * a4.w;
                *(float4*)(out + (size_t)row * MDIM + c * 64 + tx * 4) = o;
            }
        }
    }
}

extern "C" void kernel_launch(void* const* d_in, const int* in_sizes, int n_in,
                              void* d_out, int out_size) {
    const float* ck   = (const float*)d_in[0];
    const float* qa   = (const float*)d_in[1];
    const float* mk   = (const float*)d_in[2];
    const float* mv   = (const float*)d_in[3];
    const float* We   = (const float*)d_in[4];
    const float* be   = (const float*)d_in[5];
    const float* Wemv = (const float*)d_in[6];
    const float* bemv = (const float*)d_in[7];
    const float* Wza  = (const float*)d_in[8];
    const float* bza  = (const float*)d_in[9];
    const float* Wamv = (const float*)d_in[10];
    const float* bamv = (const float*)d_in[11];
    const float* Wc0  = (const float*)d_in[12];
    const float* bc0  = (const float*)d_in[13];
    const float* Wm1  = (const float*)d_in[14];
    const float* bm1  = (const float*)d_in[15];
    const float* Wz   = (const float*)d_in[16];
    const float* bz   = (const float*)d_in[17];
    const float* Wzmv = (const float*)d_in[18];
    const float* bzmv = (const float*)d_in[19];
    float* out = (float*)d_out;

    const int smem_bytes = SMEM_FLOATS * (int)sizeof(float);  // 105472
    cudaFuncSetAttribute(memnet_tc, cudaFuncAttributeMaxDynamicSharedMemorySize,
                         smem_bytes);
    cudaFuncSetAttribute(memnet_tc, cudaFuncAttributePreferredSharedMemoryCarveout, 100);

    memnet_tc<<<NROW / 64, 256, smem_bytes>>>(
        ck, qa, mk, mv, We, be, Wemv, bemv, Wza, bza, Wamv, bamv,
        Wc0, bc0, Wm1, bm1, Wz, bz, Wzmv, bzmv, out);
}

// round 16
// speedup vs baseline: 1.1182x; 1.1182x over previous
#include <cuda_runtime.h>
#include <cstdint>

#define NROW 16384      // B
#define MDIM 4096       // M*DV

// 256 MB scratch for memory_pre (fp32, exact output base)
__device__ float g_mpre[(size_t)NROW * MDIM];

__device__ __forceinline__ float sigf(float x) { return 1.0f / (1.0f + __expf(-x)); }

// m16n8k8 tf32 MMA, D accumulates in place. Raw fp32 registers are passed;
// the tensor core reads only the tf32 bits (implicit truncation).
__device__ __forceinline__ void mma8(float* c, float a0, float a1, float a2, float a3,
                                     float b0, float b1) {
    asm volatile(
        "mma.sync.aligned.m16n8k8.row.col.f32.tf32.tf32.f32 "
        "{%0,%1,%2,%3}, {%4,%5,%6,%7}, {%8,%9}, {%0,%1,%2,%3};\n"
        : "+f"(c[0]), "+f"(c[1]), "+f"(c[2]), "+f"(c[3])
        : "r"(__float_as_uint(a0)), "r"(__float_as_uint(a1)),
          "r"(__float_as_uint(a2)), "r"(__float_as_uint(a3)),
          "r"(__float_as_uint(b0)), "r"(__float_as_uint(b1)));
}

// 16-byte async copy global -> shared (LDGSTS)
__device__ __forceinline__ void cpa16(uint32_t dst, const void* src) {
    asm volatile("cp.async.cg.shared.global [%0], [%1], 16;\n" :: "r"(dst), "l"(src));
}
#define CP_COMMIT() asm volatile("cp.async.commit_group;\n" ::: "memory")
#define CP_WAIT0()  asm volatile("cp.async.wait_group 0;\n" ::: "memory")
#define CP_WAIT1()  asm volatile("cp.async.wait_group 1;\n" ::: "memory")

// Shared memory regions (float offsets). A-operand arrays use LD % 32 == 4,
// B-operand (weight) arrays use LD % 32 == 8 -> conflict-free fragment loads.
#define OFF_A 0                    // 64x132 content0; later reused as [64][68] E/erase
#define OFF_B 8448                 // weights (<=13568 floats); +4608 ck; +8960 logits/ww
#define OFF_C (8448 + 13568)       // 22016: [64][68] mv/mp/zt/aA/add (A-operand, LD 68)
#define SMEM_FLOATS (OFF_C + 4352) // 26368 floats = 105472 bytes

__global__ void __launch_bounds__(256, 2)
memnet_tc(const float* __restrict__ ck, const float* __restrict__ qa,
          const float* __restrict__ mk, const float* __restrict__ mv,
          const float* __restrict__ We, const float* __restrict__ be,
          const float* __restrict__ Wemv, const float* __restrict__ bemv,
          const float* __restrict__ Wza, const float* __restrict__ bza,
          const float* __restrict__ Wamv, const float* __restrict__ bamv,
          const float* __restrict__ Wc0, const float* __restrict__ bc0,
          const float* __restrict__ Wm1, const float* __restrict__ bm1,
          const float* __restrict__ Wz, const float* __restrict__ bz,
          const float* __restrict__ Wzmv, const float* __restrict__ bzmv,
          float* __restrict__ out)
{
    extern __shared__ float sm[];
    const uint32_t smb = (uint32_t)__cvta_generic_to_shared(sm);
    const int tid = threadIdx.x;
    const int w = tid >> 5;
    const int lane = tid & 31;
    const int g = lane >> 2;         // 0..7
    const int t = lane & 3;          // 0..3
    const int rb = blockIdx.x * 64;

    // warp tilings
    // phase0: warp grid 2(m) x 2(n) x 2(k-split); each warp m32 x n64, K-half 32
    const int wm0 = (w & 1) * 32, wn0 = ((w >> 1) & 1) * 64, kh0 = (w >> 2) * 32;
    const int wm1 = (w & 3) * 16, wn1 = (w >> 2) * 32;   // T2: m16 x n32 (out 64x64)
    const int wmE = (w & 1) * 32, wnE = (w >> 1) * 48;   // EZA: m32 x n48 (out 64x192)

    // =================== Phase 0: content0 ===================
    float acc0[2][8][4];
#pragma unroll
    for (int mi = 0; mi < 2; mi++)
#pragma unroll
        for (int j = 0; j < 8; j++)
#pragma unroll
            for (int e = 0; e < 4; e++) acc0[mi][j][e] = 0.0f;

#pragma unroll 1
    for (int c = 0; c < 64; c++) {
        __syncthreads();
        // stage mv chunk -> C [64][68] and Wc0 chunk -> B [64][136] via cp.async
#pragma unroll
        for (int l = 0; l < 4; l++) {
            int idx = tid + l * 256, r = idx >> 4, k4 = idx & 15;
            cpa16(smb + (uint32_t)(OFF_C + r * 68 + k4 * 4) * 4,
                  mv + (size_t)(rb + r) * MDIM + c * 64 + k4 * 4);
        }
#pragma unroll
        for (int l = 0; l < 8; l++) {
            int idx = tid + l * 256, k = idx >> 5, n4 = idx & 31;
            cpa16(smb + (uint32_t)(OFF_B + k * 136 + n4 * 4) * 4,
                  Wc0 + (size_t)(c * 64 + k) * 128 + n4 * 4);
        }
        CP_COMMIT(); CP_WAIT0();
        __syncthreads();
        const float* A = sm + OFF_C;
        const float* Bw = sm + OFF_B;
#pragma unroll
        for (int k8 = 0; k8 < 4; k8++) {
            int kk = kh0 + k8 * 8 + t;
            float a[2][4];
#pragma unroll
            for (int mi = 0; mi < 2; mi++) {
                int r = wm0 + mi * 16 + g;
                a[mi][0] = A[r * 68 + kk];
                a[mi][1] = A[(r + 8) * 68 + kk];
                a[mi][2] = A[r * 68 + kk + 4];
                a[mi][3] = A[(r + 8) * 68 + kk + 4];
            }
#pragma unroll
            for (int j = 0; j < 8; j++) {
                float b0 = Bw[kk * 136 + wn0 + j * 8 + g];
                float b1 = Bw[(kk + 4) * 136 + wn0 + j * 8 + g];
                mma8(acc0[0][j], a[0][0], a[0][1], a[0][2], a[0][3], b0, b1);
                mma8(acc0[1][j], a[1][0], a[1][1], a[1][2], a[1][3], b0, b1);
            }
        }
    }
    // K-split reduction: warps 4-7 dump partials into OFF_B, warps 0-3 add.
    __syncthreads();
    if (w >= 4) {
#pragma unroll
        for (int mi = 0; mi < 2; mi++)
#pragma unroll
            for (int j = 0; j < 8; j++)
#pragma unroll
                for (int ee = 0; ee < 4; ee++) {
                    int r = wm0 + mi * 16 + g + ((ee >= 2) ? 8 : 0);
                    int col = wn0 + j * 8 + 2 * t + (ee & 1);
                    sm[OFF_B + r * 136 + col] = acc0[mi][j][ee];
                }
    }
    __syncthreads();
    if (w < 4) {
#pragma unroll
        for (int mi = 0; mi < 2; mi++)
#pragma unroll
            for (int j = 0; j < 8; j++)
#pragma unroll
                for (int ee = 0; ee < 4; ee++) {
                    int r = wm0 + mi * 16 + g + ((ee >= 2) ? 8 : 0);
                    int col = wn0 + j * 8 + 2 * t + (ee & 1);
                    acc0[mi][j][ee] += sm[OFF_B + r * 136 + col];
                }
        // content0 epilogue -> s_c0 [64][132] (raw fp32; MMA truncates on use)
#pragma unroll
        for (int mi = 0; mi < 2; mi++)
#pragma unroll
            for (int j = 0; j < 8; j++)
#pragma unroll
                for (int e = 0; e < 2; e++) {
                    int col = wn0 + j * 8 + 2 * t + e;
                    float bc = bc0[col];
                    int r = wm0 + mi * 16 + g;
                    float q0 = qa[(size_t)(rb + r) * 128 + col];
                    float q1 = qa[(size_t)(rb + r + 8) * 128 + col];
                    sm[OFF_A + r * 132 + col]       = q0 * sigf(acc0[mi][j][e] + bc);
                    sm[OFF_A + (r + 8) * 132 + col] = q1 * sigf(acc0[mi][j][2 + e] + bc);
                }
    }

    // =================== Phase 1: gate + memory_pre + EZA reductions ===================
    float aE[2][6][4];
#pragma unroll
    for (int mi = 0; mi < 2; mi++)
#pragma unroll
        for (int j = 0; j < 6; j++)
#pragma unroll
            for (int e = 0; e < 4; e++) aE[mi][j][e] = 0.0f;

#pragma unroll 1
    for (int c = 0; c < 64; c++) {
        __syncthreads();   // (a): EZA(c-1) done reading B (W3) and C (mp)
        // Wm1 group FIRST (L2-resident, needed by gate)
#pragma unroll
        for (int h = 0; h < 8; h++) {
            int idx = tid + h * 256, k = idx >> 4, n4 = idx & 15;
            cpa16(smb + (uint32_t)(OFF_B + k * 72 + n4 * 4) * 4,
                  Wm1 + (size_t)k * MDIM + c * 64 + n4 * 4);
        }
        CP_COMMIT();
        // mv group SECOND (DRAM stream) -> C; stays in flight during gate GEMM
#pragma unroll
        for (int l = 0; l < 4; l++) {
            int idx = tid + l * 256, r = idx >> 4, k4 = idx & 15;
            cpa16(smb + (uint32_t)(OFF_C + r * 68 + k4 * 4) * 4,
                  mv + (size_t)(rb + r) * MDIM + c * 64 + k4 * 4);
        }
        CP_COMMIT();
        CP_WAIT1();        // Wm1 done; mv may still fly
        __syncthreads();   // (b): all threads' Wm1 visible
        // gate GEMM (T2): A = content0 (K=128), B = Wm1 chunk  [hides mv latency]
        float gg[4][4];
#pragma unroll
        for (int j = 0; j < 4; j++)
#pragma unroll
            for (int e = 0; e < 4; e++) gg[j][e] = 0.0f;
        {
            const float* A = sm + OFF_A;
            const float* Bw = sm + OFF_B;
#pragma unroll
            for (int k8 = 0; k8 < 16; k8++) {
                int kk = k8 * 8 + t;
                int r = wm1 + g;
                float a0 = A[r * 132 + kk], a1 = A[(r + 8) * 132 + kk];
                float a2 = A[r * 132 + kk + 4], a3 = A[(r + 8) * 132 + kk + 4];
#pragma unroll
                for (int j = 0; j < 4; j++) {
                    float b0 = Bw[kk * 72 + wn1 + j * 8 + g];
                    float b1 = Bw[(kk + 4) * 72 + wn1 + j * 8 + g];
                    mma8(gg[j], a0, a1, a2, a3, b0, b1);
                }
            }
        }
        CP_WAIT0();        // own mv copies done
        __syncthreads();   // (b2): all mv visible; all threads past gate (B free)
        // issue W3 cp.async NOW (hidden under mp math + mpre copy)
#pragma unroll
        for (int l = 0; l < 4; l++) {
            int idx = tid + l * 256, k = idx >> 4, d4 = idx & 15;
            size_t go = (size_t)(c * 64 + k) * 64 + d4 * 4;
            uint32_t base = smb + (uint32_t)(OFF_B + k * 200 + d4 * 4) * 4;
            cpa16(base,           Wemv + go);
            cpa16(base + 64 * 4,  Wzmv + go);
            cpa16(base + 128 * 4, Wamv + go);
        }
        CP_COMMIT();
        // memory_pre in-place in C (each cell owned by exactly one thread)
#pragma unroll
        for (int j = 0; j < 4; j++) {
            int colb = wn1 + j * 8 + 2 * t;
            float2 bm = *(const float2*)(bm1 + c * 64 + colb);
            int ra = wm1 + g, rc = wm1 + g + 8;
            float2 m0 = *(const float2*)(sm + OFF_C + ra * 68 + colb);
            float2 m1 = *(const float2*)(sm + OFF_C + rc * 68 + colb);
            float2 p0, p1;
            p0.x = m0.x * sigf(gg[j][0] + bm.x);
            p0.y = m0.y * sigf(gg[j][1] + bm.y);
            p1.x = m1.x * sigf(gg[j][2] + bm.x);
            p1.y = m1.y * sigf(gg[j][3] + bm.y);
            *(float2*)(sm + OFF_C + ra * 68 + colb) = p0;
            *(float2*)(sm + OFF_C + rc * 68 + colb) = p1;
        }
        __syncthreads();   // (c): mp visible to all
        // copy mp -> g_mpre (coalesced) while W3 copies are in flight
        {
            float4 mbuf[4];
#pragma unroll
            for (int l = 0; l < 4; l++) {
                int idx = tid + l * 256, r = idx >> 4, k4 = idx & 15;
                mbuf[l] = *(const float4*)(sm + OFF_C + r * 68 + k4 * 4);
            }
#pragma unroll
            for (int l = 0; l < 4; l++) {
                int idx = tid + l * 256, r = idx >> 4, k4 = idx & 15;
                *(float4*)(g_mpre + (size_t)(rb + r) * MDIM + c * 64 + k4 * 4) = mbuf[l];
            }
        }
        CP_WAIT0();
        __syncthreads();   // (d)
        // EZA GEMM: A = mp (raw fp32), B = [We|Wz|Wa]mv chunk, K=64
        {
            const float* A = sm + OFF_C;
            const float* Bw = sm + OFF_B;
#pragma unroll
            for (int k8 = 0; k8 < 8; k8++) {
                int kk = k8 * 8 + t;
                float a[2][4];
#pragma unroll
                for (int mi = 0; mi < 2; mi++) {
                    int r = wmE + mi * 16 + g;
                    a[mi][0] = A[r * 68 + kk];
                    a[mi][1] = A[(r + 8) * 68 + kk];
                    a[mi][2] = A[r * 68 + kk + 4];
                    a[mi][3] = A[(r + 8) * 68 + kk + 4];
                }
#pragma unroll
                for (int j = 0; j < 6; j++) {
                    float b0 = Bw[kk * 200 + wnE + j * 8 + g];
                    float b1 = Bw[(kk + 4) * 200 + wnE + j * 8 + g];
                    mma8(aE[0][j], a[0][0], a[0][1], a[0][2], a[0][3], b0, b1);
                    mma8(aE[1][j], a[1][0], a[1][1], a[1][2], a[1][3], b0, b1);
                }
            }
        }
    }
    __syncthreads();

    // =================== Epilogue ===================
    // qe = content0 @ We (K=128)
#pragma unroll
    for (int l = 0; l < 8; l++) {
        int idx = tid + l * 256, k = idx >> 4, n4 = idx & 15;
        *(float4*)(sm + OFF_B + k * 72 + n4 * 4) =
            *(const float4*)(We + (size_t)k * 64 + n4 * 4);
    }
    __syncthreads();
    float qe[4][4];
#pragma unroll
    for (int j = 0; j < 4; j++)
#pragma unroll
        for (int e = 0; e < 4; e++) qe[j][e] = 0.0f;
    {
        const float* A = sm + OFF_A;
        const float* Bw = sm + OFF_B;
#pragma unroll
        for (int k8 = 0; k8 < 16; k8++) {
            int kk = k8 * 8 + t;
            int r = wm1 + g;
            float a0 = A[r * 132 + kk], a1 = A[(r + 8) * 132 + kk];
            float a2 = A[r * 132 + kk + 4], a3 = A[(r + 8) * 132 + kk + 4];
#pragma unroll
            for (int j = 0; j < 4; j++) {
                float b0 = Bw[kk * 72 + wn1 + j * 8 + g];
                float b1 = Bw[(kk + 4) * 72 + wn1 + j * 8 + g];
                mma8(qe[j], a0, a1, a2, a3, b0, b1);
            }
        }
    }
    __syncthreads();
    // qz = content0 @ Wz
#pragma unroll
    for (int l = 0; l < 8; l++) {
        int idx = tid + l * 256, k = idx >> 4, n4 = idx & 15;
        *(float4*)(sm + OFF_B + k * 72 + n4 * 4) =
            *(const float4*)(Wz + (size_t)k * 64 + n4 * 4);
    }
    __syncthreads();
    float qz[4][4];
#pragma unroll
    for (int j = 0; j < 4; j++)
#pragma unroll
        for (int e = 0; e < 4; e++) qz[j][e] = 0.0f;
    {
        const float* A = sm + OFF_A;
        const float* Bw = sm + OFF_B;
#pragma unroll
        for (int k8 = 0; k8 < 16; k8++) {
            int kk = k8 * 8 + t;
            int r = wm1 + g;
            float a0 = A[r * 132 + kk], a1 = A[(r + 8) * 132 + kk];
            float a2 = A[r * 132 + kk + 4], a3 = A[(r + 8) * 132 + kk + 4];
#pragma unroll
            for (int j = 0; j < 4; j++) {
                float b0 = Bw[kk * 72 + wn1 + j * 8 + g];
                float b1 = Bw[(kk + 4) * 72 + wn1 + j * 8 + g];
                mma8(qz[j], a0, a1, a2, a3, b0, b1);
            }
        }
    }
    __syncthreads();
    // scatter E -> region A [64][68], Z -> region C [64][68]; keep A-part in regs
#pragma unroll
    for (int mi = 0; mi < 2; mi++)
#pragma unroll
        for (int j = 0; j < 6; j++)
#pragma unroll
            for (int ee = 0; ee < 4; ee++) {
                int n = wnE + j * 8 + 2 * t + (ee & 1);
                int r = wmE + mi * 16 + g + ((ee >= 2) ? 8 : 0);
                float v = aE[mi][j][ee];
                if (n < 64)       sm[OFF_A + r * 68 + n] = v;
                else if (n < 128) sm[OFF_C + r * 68 + (n - 64)] = v;
            }
    __syncthreads();
    // erase & zt at T2 positions (in-place rewrite by owner thread)
#pragma unroll
    for (int j = 0; j < 4; j++)
#pragma unroll
        for (int e = 0; e < 2; e++) {
            int col = wn1 + j * 8 + 2 * t + e;
            float bev = be[col], bem = bemv[col];
            float bzv = bz[col], bzm = bzmv[col];
#pragma unroll
            for (int rr = 0; rr < 2; rr++) {
                int r = wm1 + g + rr * 8;
                int ci = rr * 2 + e;
                float E = sm[OFF_A + r * 68 + col];
                float Z = sm[OFF_C + r * 68 + col];
                float er = sigf(sigf(qe[j][ci] + bev) + sigf(E + bem));
                float zt = sigf(qz[j][ci] + bzv + Z + bzm);
                sm[OFF_A + r * 68 + col] = er;
                sm[OFF_C + r * 68 + col] = zt;
            }
        }
    __syncthreads();
    // mk^T -> B[0:4608], ck -> B+4608 [64][68]
#pragma unroll
    for (int l = 0; l < 4; l++) {
        int idx = tid + l * 256, m = idx >> 4, k4 = idx & 15;
        float4 v = *(const float4*)(mk + (size_t)m * 64 + k4 * 4);
        sm[OFF_B + (k4 * 4 + 0) * 72 + m] = v.x;
        sm[OFF_B + (k4 * 4 + 1) * 72 + m] = v.y;
        sm[OFF_B + (k4 * 4 + 2) * 72 + m] = v.z;
        sm[OFF_B + (k4 * 4 + 3) * 72 + m] = v.w;
        *(float4*)(sm + OFF_B + 4608 + m * 68 + k4 * 4) =
            *(const float4*)(ck + (size_t)(rb + m) * 64 + k4 * 4);
    }
    __syncthreads();
    // logits = ck @ mk^T (K=64) -> B+8960 [64][68]
    {
        float lg[4][4];
#pragma unroll
        for (int j = 0; j < 4; j++)
#pragma unroll
            for (int e = 0; e < 4; e++) lg[j][e] = 0.0f;
        const float* A = sm + OFF_B + 4608;
        const float* Bw = sm + OFF_B;
#pragma unroll
        for (int k8 = 0; k8 < 8; k8++) {
            int kk = k8 * 8 + t;
            int r = wm1 + g;
            float a0 = A[r * 68 + kk], a1 = A[(r + 8) * 68 + kk];
            float a2 = A[r * 68 + kk + 4], a3 = A[(r + 8) * 68 + kk + 4];
#pragma unroll
            for (int j = 0; j < 4; j++) {
                float b0 = Bw[kk * 72 + wn1 + j * 8 + g];
                float b1 = Bw[(kk + 4) * 72 + wn1 + j * 8 + g];
                mma8(lg[j], a0, a1, a2, a3, b0, b1);
            }
        }
#pragma unroll
        for (int j = 0; j < 4; j++)
#pragma unroll
            for (int ee = 0; ee < 4; ee++) {
                int col = wn1 + j * 8 + 2 * t + (ee & 1);
                int r = wm1 + g + ((ee >= 2) ? 8 : 0);
                sm[OFF_B + 8960 + r * 68 + col] = lg[j][ee];
            }
    }
    __syncthreads();
    // row softmax over 64 slots -> write weights (in place)
    if (tid < 64) {
        float* row = sm + OFF_B + 8960 + tid * 68;
        float mx = row[0];
        for (int s = 1; s < 64; s++) mx = fmaxf(mx, row[s]);
        float sum = 0.0f;
        for (int s = 0; s < 64; s++) { float e = __expf(row[s] - mx); row[s] = e; sum += e; }
        float inv = 1.0f / sum;
        for (int s = 0; s < 64; s++) row[s] *= inv;
    }
    __syncthreads();
    // Wza -> B[0:4608]
#pragma unroll
    for (int l = 0; l < 4; l++) {
        int idx = tid + l * 256, k = idx >> 4, d4 = idx & 15;
        *(float4*)(sm + OFF_B + k * 72 + d4 * 4) =
            *(const float4*)(Wza + (size_t)k * 64 + d4 * 4);
    }
    __syncthreads();
    // za = zt @ Wza (K=64)
    float za[4][4];
#pragma unroll
    for (int j = 0; j < 4; j++)
#pragma unroll
        for (int e = 0; e < 4; e++) za[j][e] = 0.0f;
    {
        const float* A = sm + OFF_C;
        const float* Bw = sm + OFF_B;
#pragma unroll
        for (int k8 = 0; k8 < 8; k8++) {
            int kk = k8 * 8 + t;
            int r = wm1 + g;
            float a0 = A[r * 68 + kk], a1 = A[(r + 8) * 68 + kk];
            float a2 = A[r * 68 + kk + 4], a3 = A[(r + 8) * 68 + kk + 4];
#pragma unroll
            for (int j = 0; j < 4; j++) {
                float b0 = Bw[kk * 72 + wn1 + j * 8 + g];
                float b1 = Bw[(kk + 4) * 72 + wn1 + j * 8 + g];
                mma8(za[j], a0, a1, a2, a3, b0, b1);
            }
        }
    }
    __syncthreads();
    // scatter A-part of EZA -> region C (overwrites consumed zt)
#pragma unroll
    for (int mi = 0; mi < 2; mi++)
#pragma unroll
        for (int j = 0; j < 6; j++)
#pragma unroll
            for (int ee = 0; ee < 4; ee++) {
                int n = wnE + j * 8 + 2 * t + (ee & 1);
                if (n >= 128) {
                    int r = wmE + mi * 16 + g + ((ee >= 2) ? 8 : 0);
                    sm[OFF_C + r * 68 + (n - 128)] = aE[mi][j][ee];
                }
            }
    __syncthreads();
    // add signal at T2 positions (in-place)
#pragma unroll
    for (int j = 0; j < 4; j++)
#pragma unroll
        for (int e = 0; e < 2; e++) {
            int col = wn1 + j * 8 + 2 * t + e;
            float bzav = bza[col], bam = bamv[col];
#pragma unroll
            for (int rr = 0; rr < 2; rr++) {
                int r = wm1 + g + rr * 8;
                int ci = rr * 2 + e;
                float Aa = sm[OFF_C + r * 68 + col];
                float ad = tanhf(tanhf(za[j][ci] + bzav) + tanhf(Aa + bam));
                sm[OFF_C + r * 68 + col] = ad;
            }
        }
    __syncthreads();

    // =================== Final pass ===================
    {
        const int tx = tid & 15, ty = tid >> 4;
#pragma unroll 1
        for (int c = 0; c < 64; c++) {
#pragma unroll
            for (int i = 0; i < 4; i++) {
                int r = ty * 4 + i;
                int row = rb + r;
                float wv = sm[OFF_B + 8960 + r * 68 + c];
                float4 mp = *(const float4*)(g_mpre + (size_t)row * MDIM + c * 64 + tx * 4);
                float4 e4 = *(const float4*)(sm + OFF_A + r * 68 + tx * 4);
                float4 a4 = *(const float4*)(sm + OFF_C + r * 68 + tx * 4);
                float4 o;
                o.x = mp.x * (1.0f - wv * e4.x) + wv * a4.x;
                o.y = mp.y * (1.0f - wv * e4.y) + wv * a4.y;
                o.z = mp.z * (1.0f - wv * e4.z) + wv * a4.z;
                o.w = mp.w * (1.0f - wv * e4.w) + wv * a4.w;
                *(float4*)(out + (size_t)row * MDIM + c * 64 + tx * 4) = o;
            }
        }
    }
}

extern "C" void kernel_launch(void* const* d_in, const int* in_sizes, int n_in,
                              void* d_out, int out_size) {
    const float* ck   = (const float*)d_in[0];
    const float* qa   = (const float*)d_in[1];
    const float* mk   = (const float*)d_in[2];
    const float* mv   = (const float*)d_in[3];
    const float* We   = (const float*)d_in[4];
    const float* be   = (const float*)d_in[5];
    const float* Wemv = (const float*)d_in[6];
    const float* bemv = (const float*)d_in[7];
    const float* Wza  = (const float*)d_in[8];
    const float* bza  = (const float*)d_in[9];
    const float* Wamv = (const float*)d_in[10];
    const float* bamv = (const float*)d_in[11];
    const float* Wc0  = (const float*)d_in[12];
    const float* bc0  = (const float*)d_in[13];
    const float* Wm1  = (const float*)d_in[14];
    const float* bm1  = (const float*)d_in[15];
    const float* Wz   = (const float*)d_in[16];
    const float* bz   = (const float*)d_in[17];
    const float* Wzmv = (const float*)d_in[18];
    const float* bzmv = (const float*)d_in[19];
    float* out = (float*)d_out;

    const int smem_bytes = SMEM_FLOATS * (int)sizeof(float);  // 105472
    cudaFuncSetAttribute(memnet_tc, cudaFuncAttributeMaxDynamicSharedMemorySize,
                         smem_bytes);
    cudaFuncSetAttribute(memnet_tc, cudaFuncAttributePreferredSharedMemoryCarveout, 100);

    memnet_tc<<<NROW / 64, 256, smem_bytes>>>(
        ck, qa, mk, mv, We, be, Wemv, bemv, Wza, bza, Wamv, bamv,
        Wc0, bc0, Wm1, bm1, Wz, bz, Wzmv, bzmv, out);
}